// round 8
// baseline (speedup 1.0000x reference)
#include <cuda_runtime.h>
#include <cstdint>

// FConvLayer: irfft(rfft(x)*rfft(w_pad)) ortho == circular depthwise conv / 64.
// y[b,t,h] = (1/64) * sum_{k<16} w[k,h] * x[b,(t-k) mod 4096,h]
// out = LayerNorm_H(y + x) * ln_w + ln_b
//
// R7: scatter conv + cp.async FIFO + LDS prefetch + split SHFL butterfly.
//  - 1 warp = 128-row t-strip; lane l owns h in [4l,4l+4) (two f32x2 pairs).
//  - ring LDS for row t+1 prefetched during row t (wait depth DEPTH-2).
//  - butterfly split: stages {16,8} at row t, stages {4,2,1}+LN at row t+1,
//    so no dependent SHFL segment exceeds 3 stages.
//  - rolling global pointers for refill + store (no per-row IMAD).

typedef unsigned long long u64;
#define DINL __device__ __forceinline__

DINL u64 pack2(float lo, float hi) {
    u64 r; asm("mov.b64 %0, {%1,%2};" : "=l"(r) : "f"(lo), "f"(hi)); return r;
}
DINL void unpack2(u64 v, float& lo, float& hi) {
    asm("mov.b64 {%0,%1}, %2;" : "=f"(lo), "=f"(hi) : "l"(v));
}
DINL u64 fma2(u64 a, u64 b, u64 c) {
    u64 d; asm("fma.rn.f32x2 %0,%1,%2,%3;" : "=l"(d) : "l"(a), "l"(b), "l"(c)); return d;
}
DINL u64 add2(u64 a, u64 b) {
    u64 d; asm("add.rn.f32x2 %0,%1,%2;" : "=l"(d) : "l"(a), "l"(b)); return d;
}
DINL u64 sub2(u64 a, u64 b) {
    u64 d; asm("sub.rn.f32x2 %0,%1,%2;" : "=l"(d) : "l"(a), "l"(b)); return d;
}
DINL u64 mul2(u64 a, u64 b) {
    u64 d; asm("mul.rn.f32x2 %0,%1,%2;" : "=l"(d) : "l"(a), "l"(b)); return d;
}
DINL void stcs2(void* p, u64 a, u64 b) {
    asm volatile("st.global.cs.v2.b64 [%0], {%1,%2};"
                 :: "l"(p), "l"(a), "l"(b) : "memory");
}

#define CP16(smem_u32, gptr) \
    asm volatile("cp.async.cg.shared.global [%0], [%1], 16;" \
                 :: "r"(smem_u32), "l"(gptr) : "memory")
#define CP_COMMIT() asm volatile("cp.async.commit_group;" ::: "memory")
#define CP_WAIT(n)  asm volatile("cp.async.wait_group %0;" :: "n"(n) : "memory")

constexpr int S_LEN = 4096;
constexpr int H_DIM = 128;
constexpr int K_SZ  = 16;
constexpr int LROWS = 128;            // rows per warp strip
constexpr int DEPTH = 16;             // SMEM ring slots per warp
constexpr int ROW_B = H_DIM * 4;      // 512 bytes per row
constexpr int ROW_V = H_DIM / 4;      // 32 ulonglong2 per row

// Finish previous row from bfp (already reduced through stages 16,8):
// stages 4,2,1 + normalize + streaming store at wr_g; advance wr_g.
#define FINISH_PREV()                                                         \
    do {                                                                      \
        u64 r_ = add2(bfp, __shfl_xor_sync(0xffffffffu, bfp, 4));             \
        r_ = add2(r_, __shfl_xor_sync(0xffffffffu, r_, 2));                   \
        r_ = add2(r_, __shfl_xor_sync(0xffffffffu, r_, 1));                   \
        float s_, sq_;                                                        \
        unpack2(r_, s_, sq_);                                                 \
        const float mean = s_ * (1.0f / 128.0f);                              \
        float var = fmaf(sq_, 1.0f / 128.0f, -mean * mean);                   \
        var = fmaxf(var, 0.0f);                                               \
        const float inv = rsqrtf(var + 1e-12f);                               \
        const u64 inv2  = pack2(inv, inv);                                    \
        const u64 mean2 = pack2(mean, mean);                                  \
        u64 o0 = fma2(mul2(sub2(hp0, mean2), inv2), lw[0], lb[0]);            \
        u64 o1 = fma2(mul2(sub2(hp1, mean2), inv2), lw[1], lb[1]);            \
        stcs2(wr_g, o0, o1);                                                  \
        wr_g += ROW_V;                                                        \
    } while (0)

// One row. JJ = slot index (compile-time). FIN: finish previous row.
// REFILL: issue cp.async for row t+16 into slot JJ.
#define ROW_BODY(JJ, FIN, REFILL)                                             \
    do {                                                                      \
        ulonglong2 cur = nxt;                                                 \
        CP_WAIT(DEPTH - 2);                                                   \
        nxt = *reinterpret_cast<const ulonglong2*>(                           \
            ring_c + (((JJ) + 1) & (K_SZ - 1)) * ROW_B);                      \
        if (REFILL) { CP16(ring_s + (JJ) * ROW_B, rd_g); }                    \
        CP_COMMIT();                                                          \
        rd_g += ROW_B;                                                        \
        u64 h0 = add2(fma2(w[0][0], cur.x, acc[(JJ)][0]), cur.x);             \
        u64 h1 = add2(fma2(w[0][1], cur.y, acc[(JJ)][1]), cur.y);             \
        {                                                                     \
            const int s15_ = ((JJ) + 15) & (K_SZ - 1);                        \
            acc[s15_][0] = mul2(w[15][0], cur.x);                             \
            acc[s15_][1] = mul2(w[15][1], cur.y);                             \
        }                                                                     \
        _Pragma("unroll")                                                     \
        for (int k = 1; k < K_SZ - 1; k++) {                                  \
            const int s_ = ((JJ) + k) & (K_SZ - 1);                           \
            acc[s_][0] = fma2(w[k][0], cur.x, acc[s_][0]);                    \
            acc[s_][1] = fma2(w[k][1], cur.y, acc[s_][1]);                    \
        }                                                                     \
        float f0, f1, f2, f3;                                                 \
        unpack2(h0, f0, f1);                                                  \
        unpack2(h1, f2, f3);                                                  \
        u64 ps = pack2((f0 + f1) + (f2 + f3),                                 \
                       fmaf(f0, f0, fmaf(f1, f1, fmaf(f2, f2, f3 * f3))));    \
        u64 q_ = add2(ps, __shfl_xor_sync(0xffffffffu, ps, 16));              \
        q_ = add2(q_, __shfl_xor_sync(0xffffffffu, q_, 8));                   \
        if (FIN) { FINISH_PREV(); }                                           \
        bfp = q_; hp0 = h0; hp1 = h1;                                         \
    } while (0)

__global__ void __launch_bounds__(128, 3) fconv_ln_kernel(
    const float* __restrict__ x,
    const float* __restrict__ cw,
    const float* __restrict__ lnw,
    const float* __restrict__ lnb,
    float* __restrict__ out)
{
    __shared__ __align__(16) unsigned char ring[4 * DEPTH * ROW_B];  // 32KB

    const int lane  = threadIdx.x & 31;
    const int warp  = threadIdx.x >> 5;
    const int gwarp = (blockIdx.x * blockDim.x + threadIdx.x) >> 5;
    const int spb   = S_LEN / LROWS;          // 32 strips per batch
    const int b     = gwarp / spb;
    const int t0    = (gwarp % spb) * LROWS;  // multiple of 128

    const char* __restrict__ xb =
        reinterpret_cast<const char*>(x) + (size_t)b * S_LEN * ROW_B;
    ulonglong2* wr_g =
        reinterpret_cast<ulonglong2*>(out) + (size_t)b * S_LEN * ROW_V
        + (size_t)t0 * ROW_V + lane;

    unsigned char* const ring_c = ring + warp * (DEPTH * ROW_B) + lane * 16;
    const uint32_t ring_s = (uint32_t)__cvta_generic_to_shared(ring_c);

    // ---- kick off the FIFO: rows t0..t0+15 into slots 0..15 ----
#pragma unroll
    for (int q = 0; q < DEPTH; q++) {
        CP16(ring_s + q * ROW_B, xb + (size_t)(t0 + q) * ROW_B + lane * 16);
        CP_COMMIT();
    }
    // rolling refill source: row t0+16
    const char* rd_g = xb + (size_t)(t0 + DEPTH) * ROW_B + lane * 16;

    // ---- weights, pre-scaled by 1/64, as f32x2 pairs ----
    u64 w[K_SZ][2];
    {
        const ulonglong2* cw2 = reinterpret_cast<const ulonglong2*>(cw);
        const u64 sc2 = pack2(0.015625f, 0.015625f);
#pragma unroll
        for (int k = 0; k < K_SZ; k++) {
            ulonglong2 v = cw2[k * ROW_V + lane];
            w[k][0] = mul2(v.x, sc2);
            w[k][1] = mul2(v.y, sc2);
        }
    }

    // ---- LN params ----
    u64 lw[2], lb[2];
    {
        ulonglong2 v = reinterpret_cast<const ulonglong2*>(lnw)[lane];
        lw[0] = v.x; lw[1] = v.y;
        ulonglong2 u = reinterpret_cast<const ulonglong2*>(lnb)[lane];
        lb[0] = u.x; lb[1] = u.y;
    }

    // ---- forward partial accumulators ----
    u64 acc[K_SZ][2];
#pragma unroll
    for (int i = 0; i < K_SZ; i++) { acc[i][0] = 0ull; acc[i][1] = 0ull; }

    // ---- halo: rows t0-15..t0-1 (one-time LDG) ----
    const ulonglong2* xb2 = reinterpret_cast<const ulonglong2*>(xb);
#pragma unroll
    for (int i = 0; i < K_SZ - 1; i++) {
        const int r = (t0 - (K_SZ - 1) + i + S_LEN) & (S_LEN - 1);
        ulonglong2 v = xb2[r * ROW_V + lane];
#pragma unroll
        for (int k = K_SZ - 1 - i; k < K_SZ; k++) {
            const int s = (i + 1 + k) & (K_SZ - 1);
            acc[s][0] = fma2(w[k][0], v.x, acc[s][0]);
            acc[s][1] = fma2(w[k][1], v.y, acc[s][1]);
        }
    }

    // ---- pipelined state ----
    u64 hp0 = 0ull, hp1 = 0ull, bfp = 0ull;
    ulonglong2 nxt;

    // prologue read of row t0's slot (wait leaves rows <= t0+1 complete)
    CP_WAIT(DEPTH - 2);
    nxt = *reinterpret_cast<const ulonglong2*>(ring_c);

    // ---- first block (rows 0..15): row 0 has no predecessor ----
    {
#pragma unroll
        for (int j = 0; j < K_SZ; j++) {
            if (j == 0) { ROW_BODY(j, false, true); }
            else        { ROW_BODY(j, true,  true); }
        }
    }
    // ---- middle blocks (rows 16..111): steady state, always refill ----
#pragma unroll 1
    for (int jo = K_SZ; jo < LROWS - K_SZ; jo += K_SZ) {
#pragma unroll
        for (int j = 0; j < K_SZ; j++) {
            ROW_BODY(j, true, true);
        }
    }
    // ---- last block (rows 112..127): no refill, commits keep FIFO sane ----
    {
#pragma unroll
        for (int j = 0; j < K_SZ; j++) {
            ROW_BODY(j, true, false);
        }
    }

    // ---- epilogue: finish the final row ----
    FINISH_PREV();
}

extern "C" void kernel_launch(void* const* d_in, const int* in_sizes, int n_in,
                              void* d_out, int out_size)
{
    const float* x   = (const float*)d_in[0];  // [64, 4096, 128]
    const float* cw  = (const float*)d_in[1];  // [1, 16, 128]
    const float* lnw = (const float*)d_in[2];  // [128]
    const float* lnb = (const float*)d_in[3];  // [128]
    float* out = (float*)d_out;                // [64, 4096, 128]

    const int total_warps = 64 * (S_LEN / LROWS);   // 2048
    const int blocks = total_warps / 4;             // 512
    fconv_ln_kernel<<<blocks, 128>>>(x, cw, lnw, lnb, out);
}

// round 10
// speedup vs baseline: 1.4829x; 1.4829x over previous
#include <cuda_runtime.h>
#include <cstdint>

// FConvLayer: irfft(rfft(x)*rfft(w_pad)) ortho == circular depthwise conv / 64.
// y[b,t,h] = (1/64) * sum_{k<16} w[k,h] * x[b,(t-k) mod 4096,h]
// out = LayerNorm_H(y + x) * ln_w + ln_b
//
// R8 = R6 (best, 57.4us) + LN finish deferred TWO rows (double-buffered),
//      so each 5-stage SHFL butterfly hides under two conv bodies and two
//      independent butterfly chains are in flight per warp.
//  - 1 warp = 128-row t-strip; lane l owns h in [4l,4l+4) (two f32x2 pairs).
//  - 16 forward partial accumulators (scatter form); cp.async SMEM FIFO.
//  - (sum, sumsq) packed in ONE u64; butterfly = 5x(SHFL+add2).
//  - rolling output pointer (stores strictly in row order).

typedef unsigned long long u64;
#define DINL __device__ __forceinline__

DINL u64 pack2(float lo, float hi) {
    u64 r; asm("mov.b64 %0, {%1,%2};" : "=l"(r) : "f"(lo), "f"(hi)); return r;
}
DINL void unpack2(u64 v, float& lo, float& hi) {
    asm("mov.b64 {%0,%1}, %2;" : "=f"(lo), "=f"(hi) : "l"(v));
}
DINL u64 fma2(u64 a, u64 b, u64 c) {
    u64 d; asm("fma.rn.f32x2 %0,%1,%2,%3;" : "=l"(d) : "l"(a), "l"(b), "l"(c)); return d;
}
DINL u64 add2(u64 a, u64 b) {
    u64 d; asm("add.rn.f32x2 %0,%1,%2;" : "=l"(d) : "l"(a), "l"(b)); return d;
}
DINL u64 sub2(u64 a, u64 b) {
    u64 d; asm("sub.rn.f32x2 %0,%1,%2;" : "=l"(d) : "l"(a), "l"(b)); return d;
}
DINL u64 mul2(u64 a, u64 b) {
    u64 d; asm("mul.rn.f32x2 %0,%1,%2;" : "=l"(d) : "l"(a), "l"(b)); return d;
}
DINL void stcs2(void* p, u64 a, u64 b) {
    asm volatile("st.global.cs.v2.b64 [%0], {%1,%2};"
                 :: "l"(p), "l"(a), "l"(b) : "memory");
}

#define CP16(smem_u32, gptr) \
    asm volatile("cp.async.cg.shared.global [%0], [%1], 16;" \
                 :: "r"(smem_u32), "l"(gptr) : "memory")
#define CP_COMMIT() asm volatile("cp.async.commit_group;" ::: "memory")
#define CP_WAIT(n)  asm volatile("cp.async.wait_group %0;" :: "n"(n) : "memory")

constexpr int S_LEN = 4096;
constexpr int H_DIM = 128;
constexpr int K_SZ  = 16;
constexpr int LROWS = 128;            // rows per warp strip
constexpr int DEPTH = 16;             // SMEM ring slots per warp
constexpr int ROW_B = H_DIM * 4;      // 512 bytes per row
constexpr int ROW_V = H_DIM / 4;      // 32 ulonglong2 per row

// Finish the row buffered in parity slot PP: full 5-stage butterfly on its
// packed (sum,sumsq), normalize, streaming store at wr_g (rows in order).
#define FINISH_SLOT(PP)                                                       \
    do {                                                                      \
        u64 tot = psb[(PP)];                                                  \
        _Pragma("unroll")                                                     \
        for (int off = 16; off > 0; off >>= 1)                                \
            tot = add2(tot, __shfl_xor_sync(0xffffffffu, tot, off));          \
        float s_, sq_;                                                        \
        unpack2(tot, s_, sq_);                                                \
        const float mean = s_ * (1.0f / 128.0f);                              \
        float var = fmaf(sq_, 1.0f / 128.0f, -mean * mean);                   \
        var = fmaxf(var, 0.0f);                                               \
        const float inv = rsqrtf(var + 1e-12f);                               \
        const u64 inv2  = pack2(inv, inv);                                    \
        const u64 mean2 = pack2(mean, mean);                                  \
        u64 o0 = fma2(mul2(sub2(h0b[(PP)], mean2), inv2), lw[0], lb[0]);      \
        u64 o1 = fma2(mul2(sub2(h1b[(PP)], mean2), inv2), lw[1], lb[1]);      \
        stcs2(wr_g, o0, o1);                                                  \
        wr_g += ROW_V;                                                        \
    } while (0)

// One row (slot JJ, compile-time). FIN: finish the row from TWO iterations
// ago (same parity slot), overlapping its butterfly with this conv.
#define ROW_BODY(JJ, FIN)                                                     \
    do {                                                                      \
        const int t_ = t0 + jo + (JJ);                                        \
        CP_WAIT(DEPTH - 1);                                                   \
        ulonglong2 cur =                                                      \
            *reinterpret_cast<const ulonglong2*>(ring_c + (JJ) * ROW_B);      \
        if (jo + (JJ) + DEPTH < LROWS) {                                      \
            CP16(ring_s + (JJ) * ROW_B,                                       \
                 xb + (size_t)(t_ + DEPTH) * ROW_B + lane * 16);              \
        }                                                                     \
        CP_COMMIT();                                                          \
        u64 h0 = add2(fma2(w[0][0], cur.x, acc[(JJ)][0]), cur.x);             \
        u64 h1 = add2(fma2(w[0][1], cur.y, acc[(JJ)][1]), cur.y);             \
        {                                                                     \
            const int s15_ = ((JJ) + 15) & (K_SZ - 1);                        \
            acc[s15_][0] = mul2(w[15][0], cur.x);                             \
            acc[s15_][1] = mul2(w[15][1], cur.y);                             \
        }                                                                     \
        _Pragma("unroll")                                                     \
        for (int k = 1; k < K_SZ - 1; k++) {                                  \
            const int s_ = ((JJ) + k) & (K_SZ - 1);                           \
            acc[s_][0] = fma2(w[k][0], cur.x, acc[s_][0]);                    \
            acc[s_][1] = fma2(w[k][1], cur.y, acc[s_][1]);                    \
        }                                                                     \
        float f0, f1, f2, f3;                                                 \
        unpack2(h0, f0, f1);                                                  \
        unpack2(h1, f2, f3);                                                  \
        u64 ps = pack2((f0 + f1) + (f2 + f3),                                 \
                       fmaf(f0, f0, fmaf(f1, f1, fmaf(f2, f2, f3 * f3))));    \
        if (FIN) { FINISH_SLOT((JJ) & 1); }                                   \
        psb[(JJ) & 1] = ps;                                                   \
        h0b[(JJ) & 1] = h0;                                                   \
        h1b[(JJ) & 1] = h1;                                                   \
    } while (0)

__global__ void __launch_bounds__(128, 3) fconv_ln_kernel(
    const float* __restrict__ x,
    const float* __restrict__ cw,
    const float* __restrict__ lnw,
    const float* __restrict__ lnb,
    float* __restrict__ out)
{
    __shared__ __align__(16) unsigned char ring[4 * DEPTH * ROW_B];  // 32KB

    const int lane  = threadIdx.x & 31;
    const int warp  = threadIdx.x >> 5;
    const int gwarp = (blockIdx.x * blockDim.x + threadIdx.x) >> 5;
    const int spb   = S_LEN / LROWS;          // 32 strips per batch
    const int b     = gwarp / spb;
    const int t0    = (gwarp % spb) * LROWS;  // multiple of 128

    const char* __restrict__ xb =
        reinterpret_cast<const char*>(x) + (size_t)b * S_LEN * ROW_B;
    ulonglong2* wr_g =
        reinterpret_cast<ulonglong2*>(out) + (size_t)b * S_LEN * ROW_V
        + (size_t)t0 * ROW_V + lane;

    unsigned char* const ring_c = ring + warp * (DEPTH * ROW_B) + lane * 16;
    const uint32_t ring_s = (uint32_t)__cvta_generic_to_shared(ring_c);

    // ---- weights, pre-scaled by 1/64, as f32x2 pairs ----
    u64 w[K_SZ][2];
    {
        const ulonglong2* cw2 = reinterpret_cast<const ulonglong2*>(cw);
        const u64 sc2 = pack2(0.015625f, 0.015625f);
#pragma unroll
        for (int k = 0; k < K_SZ; k++) {
            ulonglong2 v = cw2[k * ROW_V + lane];
            w[k][0] = mul2(v.x, sc2);
            w[k][1] = mul2(v.y, sc2);
        }
    }

    // ---- LN params ----
    u64 lw[2], lb[2];
    {
        ulonglong2 v = reinterpret_cast<const ulonglong2*>(lnw)[lane];
        lw[0] = v.x; lw[1] = v.y;
        ulonglong2 u = reinterpret_cast<const ulonglong2*>(lnb)[lane];
        lb[0] = u.x; lb[1] = u.y;
    }

    // ---- kick off the FIFO: rows t0..t0+15 into slots 0..15 ----
#pragma unroll
    for (int q = 0; q < DEPTH; q++) {
        CP16(ring_s + q * ROW_B, xb + (size_t)(t0 + q) * ROW_B + lane * 16);
        CP_COMMIT();
    }

    // ---- forward partial accumulators ----
    u64 acc[K_SZ][2];
#pragma unroll
    for (int i = 0; i < K_SZ; i++) { acc[i][0] = 0ull; acc[i][1] = 0ull; }

    // ---- halo: rows t0-15..t0-1 (one-time LDG) ----
    const ulonglong2* xb2 = reinterpret_cast<const ulonglong2*>(xb);
#pragma unroll
    for (int i = 0; i < K_SZ - 1; i++) {
        const int r = (t0 - (K_SZ - 1) + i + S_LEN) & (S_LEN - 1);
        ulonglong2 v = xb2[r * ROW_V + lane];
#pragma unroll
        for (int k = K_SZ - 1 - i; k < K_SZ; k++) {
            const int s = (i + 1 + k) & (K_SZ - 1);
            acc[s][0] = fma2(w[k][0], v.x, acc[s][0]);
            acc[s][1] = fma2(w[k][1], v.y, acc[s][1]);
        }
    }

    // ---- 2-row double-buffered pipeline state ----
    u64 psb[2] = {0ull, 0ull};
    u64 h0b[2] = {0ull, 0ull};
    u64 h1b[2] = {0ull, 0ull};

    // ---- peel first block of 16 rows: rows 0,1 have no row to finish ----
    {
        const int jo = 0;
#pragma unroll
        for (int j = 0; j < K_SZ; j++) {
            if (j < 2) { ROW_BODY(j, false); }
            else       { ROW_BODY(j, true);  }
        }
    }
#pragma unroll 1
    for (int jo = K_SZ; jo < LROWS; jo += K_SZ) {
#pragma unroll
        for (int j = 0; j < K_SZ; j++) {
            ROW_BODY(j, true);
        }
    }

    // ---- epilogue: finish rows 126 (parity 0) and 127 (parity 1) ----
    FINISH_SLOT(0);
    FINISH_SLOT(1);
}

extern "C" void kernel_launch(void* const* d_in, const int* in_sizes, int n_in,
                              void* d_out, int out_size)
{
    const float* x   = (const float*)d_in[0];  // [64, 4096, 128]
    const float* cw  = (const float*)d_in[1];  // [1, 16, 128]
    const float* lnw = (const float*)d_in[2];  // [128]
    const float* lnb = (const float*)d_in[3];  // [128]
    float* out = (float*)d_out;                // [64, 4096, 128]

    const int total_warps = 64 * (S_LEN / LROWS);   // 2048
    const int blocks = total_warps / 4;             // 512
    fconv_ln_kernel<<<blocks, 128>>>(x, cw, lnw, lnb, out);
}

// round 12
// speedup vs baseline: 1.5134x; 1.0206x over previous
#include <cuda_runtime.h>
#include <cstdint>

// FConvLayer: irfft(rfft(x)*rfft(w_pad)) ortho == circular depthwise conv / 64.
// y[b,t,h] = (1/64) * sum_{k<16} w[k,h] * x[b,(t-k) mod 4096,h]
// out = LayerNorm_H(y + x) * ln_w + ln_b
//
// R10 = R8 (57.2us) with ONE change: LROWS 128 -> 64.
//   Grid 512 -> 1024 CTAs: wave quantization tail drops from +15.6% (512 over
//   444 resident slots -> 68 SMs run 4 CTAs) to +1.2% (1024 = 6*148 + 136).
//   Cost: halo read fraction 1.117x -> 1.234x (~+5% DRAM bytes).
//  - 1 warp = 64-row t-strip; lane l owns h in [4l,4l+4) (two f32x2 pairs).
//  - 16 forward partial accumulators (scatter form); cp.async SMEM FIFO.
//  - (sum, sumsq) packed in ONE u64; butterfly = 5x(SHFL+add2).
//  - LN finish deferred TWO rows (double-buffered) under conv fma2 streams.

typedef unsigned long long u64;
#define DINL __device__ __forceinline__

DINL u64 pack2(float lo, float hi) {
    u64 r; asm("mov.b64 %0, {%1,%2};" : "=l"(r) : "f"(lo), "f"(hi)); return r;
}
DINL void unpack2(u64 v, float& lo, float& hi) {
    asm("mov.b64 {%0,%1}, %2;" : "=f"(lo), "=f"(hi) : "l"(v));
}
DINL u64 fma2(u64 a, u64 b, u64 c) {
    u64 d; asm("fma.rn.f32x2 %0,%1,%2,%3;" : "=l"(d) : "l"(a), "l"(b), "l"(c)); return d;
}
DINL u64 add2(u64 a, u64 b) {
    u64 d; asm("add.rn.f32x2 %0,%1,%2;" : "=l"(d) : "l"(a), "l"(b)); return d;
}
DINL u64 sub2(u64 a, u64 b) {
    u64 d; asm("sub.rn.f32x2 %0,%1,%2;" : "=l"(d) : "l"(a), "l"(b)); return d;
}
DINL u64 mul2(u64 a, u64 b) {
    u64 d; asm("mul.rn.f32x2 %0,%1,%2;" : "=l"(d) : "l"(a), "l"(b)); return d;
}
DINL void stcs2(void* p, u64 a, u64 b) {
    asm volatile("st.global.cs.v2.b64 [%0], {%1,%2};"
                 :: "l"(p), "l"(a), "l"(b) : "memory");
}

#define CP16(smem_u32, gptr) \
    asm volatile("cp.async.cg.shared.global [%0], [%1], 16;" \
                 :: "r"(smem_u32), "l"(gptr) : "memory")
#define CP_COMMIT() asm volatile("cp.async.commit_group;" ::: "memory")
#define CP_WAIT(n)  asm volatile("cp.async.wait_group %0;" :: "n"(n) : "memory")

constexpr int S_LEN = 4096;
constexpr int H_DIM = 128;
constexpr int K_SZ  = 16;
constexpr int LROWS = 64;             // rows per warp strip (R10 change)
constexpr int DEPTH = 16;             // SMEM ring slots per warp
constexpr int ROW_B = H_DIM * 4;      // 512 bytes per row
constexpr int ROW_V = H_DIM / 4;      // 32 ulonglong2 per row

// Finish the row buffered in parity slot PP: full 5-stage butterfly on its
// packed (sum,sumsq), normalize, streaming store at wr_g (rows in order).
#define FINISH_SLOT(PP)                                                       \
    do {                                                                      \
        u64 tot = psb[(PP)];                                                  \
        _Pragma("unroll")                                                     \
        for (int off = 16; off > 0; off >>= 1)                                \
            tot = add2(tot, __shfl_xor_sync(0xffffffffu, tot, off));          \
        float s_, sq_;                                                        \
        unpack2(tot, s_, sq_);                                                \
        const float mean = s_ * (1.0f / 128.0f);                              \
        float var = fmaf(sq_, 1.0f / 128.0f, -mean * mean);                   \
        var = fmaxf(var, 0.0f);                                               \
        const float inv = rsqrtf(var + 1e-12f);                               \
        const u64 inv2  = pack2(inv, inv);                                    \
        const u64 mean2 = pack2(mean, mean);                                  \
        u64 o0 = fma2(mul2(sub2(h0b[(PP)], mean2), inv2), lw[0], lb[0]);      \
        u64 o1 = fma2(mul2(sub2(h1b[(PP)], mean2), inv2), lw[1], lb[1]);      \
        stcs2(wr_g, o0, o1);                                                  \
        wr_g += ROW_V;                                                        \
    } while (0)

// One row (slot JJ, compile-time). FIN: finish the row from TWO iterations
// ago (same parity slot), overlapping its butterfly with this conv.
#define ROW_BODY(JJ, FIN)                                                     \
    do {                                                                      \
        const int t_ = t0 + jo + (JJ);                                        \
        CP_WAIT(DEPTH - 1);                                                   \
        ulonglong2 cur =                                                      \
            *reinterpret_cast<const ulonglong2*>(ring_c + (JJ) * ROW_B);      \
        if (jo + (JJ) + DEPTH < LROWS) {                                      \
            CP16(ring_s + (JJ) * ROW_B,                                       \
                 xb + (size_t)(t_ + DEPTH) * ROW_B + lane * 16);              \
        }                                                                     \
        CP_COMMIT();                                                          \
        u64 h0 = add2(fma2(w[0][0], cur.x, acc[(JJ)][0]), cur.x);             \
        u64 h1 = add2(fma2(w[0][1], cur.y, acc[(JJ)][1]), cur.y);             \
        {                                                                     \
            const int s15_ = ((JJ) + 15) & (K_SZ - 1);                        \
            acc[s15_][0] = mul2(w[15][0], cur.x);                             \
            acc[s15_][1] = mul2(w[15][1], cur.y);                             \
        }                                                                     \
        _Pragma("unroll")                                                     \
        for (int k = 1; k < K_SZ - 1; k++) {                                  \
            const int s_ = ((JJ) + k) & (K_SZ - 1);                           \
            acc[s_][0] = fma2(w[k][0], cur.x, acc[s_][0]);                    \
            acc[s_][1] = fma2(w[k][1], cur.y, acc[s_][1]);                    \
        }                                                                     \
        float f0, f1, f2, f3;                                                 \
        unpack2(h0, f0, f1);                                                  \
        unpack2(h1, f2, f3);                                                  \
        u64 ps = pack2((f0 + f1) + (f2 + f3),                                 \
                       fmaf(f0, f0, fmaf(f1, f1, fmaf(f2, f2, f3 * f3))));    \
        if (FIN) { FINISH_SLOT((JJ) & 1); }                                   \
        psb[(JJ) & 1] = ps;                                                   \
        h0b[(JJ) & 1] = h0;                                                   \
        h1b[(JJ) & 1] = h1;                                                   \
    } while (0)

__global__ void __launch_bounds__(128, 3) fconv_ln_kernel(
    const float* __restrict__ x,
    const float* __restrict__ cw,
    const float* __restrict__ lnw,
    const float* __restrict__ lnb,
    float* __restrict__ out)
{
    __shared__ __align__(16) unsigned char ring[4 * DEPTH * ROW_B];  // 32KB

    const int lane  = threadIdx.x & 31;
    const int warp  = threadIdx.x >> 5;
    const int gwarp = (blockIdx.x * blockDim.x + threadIdx.x) >> 5;
    const int spb   = S_LEN / LROWS;          // 64 strips per batch
    const int b     = gwarp / spb;
    const int t0    = (gwarp % spb) * LROWS;  // multiple of 64 (t0 % 16 == 0)

    const char* __restrict__ xb =
        reinterpret_cast<const char*>(x) + (size_t)b * S_LEN * ROW_B;
    ulonglong2* wr_g =
        reinterpret_cast<ulonglong2*>(out) + (size_t)b * S_LEN * ROW_V
        + (size_t)t0 * ROW_V + lane;

    unsigned char* const ring_c = ring + warp * (DEPTH * ROW_B) + lane * 16;
    const uint32_t ring_s = (uint32_t)__cvta_generic_to_shared(ring_c);

    // ---- weights, pre-scaled by 1/64, as f32x2 pairs ----
    u64 w[K_SZ][2];
    {
        const ulonglong2* cw2 = reinterpret_cast<const ulonglong2*>(cw);
        const u64 sc2 = pack2(0.015625f, 0.015625f);
#pragma unroll
        for (int k = 0; k < K_SZ; k++) {
            ulonglong2 v = cw2[k * ROW_V + lane];
            w[k][0] = mul2(v.x, sc2);
            w[k][1] = mul2(v.y, sc2);
        }
    }

    // ---- LN params ----
    u64 lw[2], lb[2];
    {
        ulonglong2 v = reinterpret_cast<const ulonglong2*>(lnw)[lane];
        lw[0] = v.x; lw[1] = v.y;
        ulonglong2 u = reinterpret_cast<const ulonglong2*>(lnb)[lane];
        lb[0] = u.x; lb[1] = u.y;
    }

    // ---- kick off the FIFO: rows t0..t0+15 into slots 0..15 ----
#pragma unroll
    for (int q = 0; q < DEPTH; q++) {
        CP16(ring_s + q * ROW_B, xb + (size_t)(t0 + q) * ROW_B + lane * 16);
        CP_COMMIT();
    }

    // ---- forward partial accumulators ----
    u64 acc[K_SZ][2];
#pragma unroll
    for (int i = 0; i < K_SZ; i++) { acc[i][0] = 0ull; acc[i][1] = 0ull; }

    // ---- halo: rows t0-15..t0-1 (one-time LDG) ----
    const ulonglong2* xb2 = reinterpret_cast<const ulonglong2*>(xb);
#pragma unroll
    for (int i = 0; i < K_SZ - 1; i++) {
        const int r = (t0 - (K_SZ - 1) + i + S_LEN) & (S_LEN - 1);
        ulonglong2 v = xb2[r * ROW_V + lane];
#pragma unroll
        for (int k = K_SZ - 1 - i; k < K_SZ; k++) {
            const int s = (i + 1 + k) & (K_SZ - 1);
            acc[s][0] = fma2(w[k][0], v.x, acc[s][0]);
            acc[s][1] = fma2(w[k][1], v.y, acc[s][1]);
        }
    }

    // ---- 2-row double-buffered pipeline state ----
    u64 psb[2] = {0ull, 0ull};
    u64 h0b[2] = {0ull, 0ull};
    u64 h1b[2] = {0ull, 0ull};

    // ---- peel first block of 16 rows: rows 0,1 have no row to finish ----
    {
        const int jo = 0;
#pragma unroll
        for (int j = 0; j < K_SZ; j++) {
            if (j < 2) { ROW_BODY(j, false); }
            else       { ROW_BODY(j, true);  }
        }
    }
#pragma unroll 1
    for (int jo = K_SZ; jo < LROWS; jo += K_SZ) {
#pragma unroll
        for (int j = 0; j < K_SZ; j++) {
            ROW_BODY(j, true);
        }
    }

    // ---- epilogue: finish rows LROWS-2 (parity 0) and LROWS-1 (parity 1) ----
    FINISH_SLOT(0);
    FINISH_SLOT(1);
}

extern "C" void kernel_launch(void* const* d_in, const int* in_sizes, int n_in,
                              void* d_out, int out_size)
{
    const float* x   = (const float*)d_in[0];  // [64, 4096, 128]
    const float* cw  = (const float*)d_in[1];  // [1, 16, 128]
    const float* lnw = (const float*)d_in[2];  // [128]
    const float* lnb = (const float*)d_in[3];  // [128]
    float* out = (float*)d_out;                // [64, 4096, 128]

    const int total_warps = 64 * (S_LEN / LROWS);   // 4096
    const int blocks = total_warps / 4;             // 1024
    fconv_ln_kernel<<<blocks, 128>>>(x, cw, lnw, lnb, out);
}